// round 3
// baseline (speedup 1.0000x reference)
#include <cuda_runtime.h>
#include <cuda_bf16.h>

#define KK 64
#define NN 4096
#define BI 64          // rows of X per block
#define CN 32          // n-chunk per smem stage
#define SPLIT 2        // split of the n (reduction) dimension
#define STK 68         // padded smem stride (float4-aligned, conflict-free reads)

// Partial row_sums: [SPLIT][KK][NN] = 2 MB scratch
__device__ float g_partial[SPLIT * KK * NN];

// ---------------------------------------------------------------------------
// GEMM: partial[s][k][i] = sum_{n in split s} zs[k][n] * X[i][n]
// ---------------------------------------------------------------------------
__global__ __launch_bounds__(256, 2)
void gemm_kernel(const float* __restrict__ zs, const float* __restrict__ X) {
    __shared__ float zsS[CN][STK];   // [n][k]
    __shared__ float xS [CN][STK];   // [n][i_local]

    const int tx = threadIdx.x & 15;       // i group (16 x 4 = 64)
    const int ty = threadIdx.x >> 4;       // k group (16 x 4 = 64)
    const int ibase = blockIdx.x * BI;
    const int nbase0 = blockIdx.y * (NN / SPLIT);

    float acc[4][4];
#pragma unroll
    for (int j = 0; j < 4; ++j)
#pragma unroll
        for (int l = 0; l < 4; ++l) acc[j][l] = 0.f;

    const int NCHUNK = (NN / SPLIT) / CN;  // 64
    for (int c = 0; c < NCHUNK; ++c) {
        const int nb = nbase0 + c * CN;

        // Cooperative load: each tile is 64 rows x 32 n = 512 float4s, 2/thread
#pragma unroll
        for (int p = 0; p < 2; ++p) {
            const int idx4 = threadIdx.x + p * 256;  // 0..511
            const int row  = idx4 >> 3;              // 0..63
            const int n4   = idx4 & 7;               // 0..7 (float4 within row)
            float4 az = *(const float4*)&zs[(size_t)row * NN + nb + n4 * 4];
            float4 ax = *(const float4*)&X[(size_t)(ibase + row) * NN + nb + n4 * 4];
            // transpose into [n][row]
            zsS[n4 * 4 + 0][row] = az.x;
            zsS[n4 * 4 + 1][row] = az.y;
            zsS[n4 * 4 + 2][row] = az.z;
            zsS[n4 * 4 + 3][row] = az.w;
            xS [n4 * 4 + 0][row] = ax.x;
            xS [n4 * 4 + 1][row] = ax.y;
            xS [n4 * 4 + 2][row] = ax.z;
            xS [n4 * 4 + 3][row] = ax.w;
        }
        __syncthreads();

#pragma unroll
        for (int n = 0; n < CN; ++n) {
            const float4 a = *(const float4*)&zsS[n][ty * 4];
            const float4 b = *(const float4*)&xS [n][tx * 4];
            acc[0][0] += a.x * b.x; acc[0][1] += a.x * b.y;
            acc[0][2] += a.x * b.z; acc[0][3] += a.x * b.w;
            acc[1][0] += a.y * b.x; acc[1][1] += a.y * b.y;
            acc[1][2] += a.y * b.z; acc[1][3] += a.y * b.w;
            acc[2][0] += a.z * b.x; acc[2][1] += a.z * b.y;
            acc[2][2] += a.z * b.z; acc[2][3] += a.z * b.w;
            acc[3][0] += a.w * b.x; acc[3][1] += a.w * b.y;
            acc[3][2] += a.w * b.z; acc[3][3] += a.w * b.w;
        }
        __syncthreads();
    }

    float* part = g_partial + (size_t)blockIdx.y * KK * NN;
#pragma unroll
    for (int j = 0; j < 4; ++j) {
        const int k = ty * 4 + j;
#pragma unroll
        for (int l = 0; l < 4; ++l) {
            const int i = ibase + tx * 4 + l;
            part[(size_t)k * NN + i] = acc[j][l];
        }
    }
}

// ---------------------------------------------------------------------------
__global__ void zero_out_kernel(float* out) { out[0] = 0.f; }

// ---------------------------------------------------------------------------
// Epilogue: sum_k,i  num/(vn+den),  num = zs[k,i]*X[i,i],
//           den = (partial0+partial1)[k,i] - num.  out = -sum/KK
// ---------------------------------------------------------------------------
__global__ __launch_bounds__(256)
void finish_kernel(const float* __restrict__ zs, const float* __restrict__ X,
                   const float* __restrict__ vn_p, float* __restrict__ out) {
    const int idx = blockIdx.x * blockDim.x + threadIdx.x;  // 0..KK*NN-1 exactly
    const float vn = *vn_p;

    const int i = idx & (NN - 1);
    const float rs  = g_partial[idx] + g_partial[idx + KK * NN];
    const float z   = zs[idx];
    const float xd  = X[(size_t)i * NN + i];
    const float num = z * xd;
    const float den = rs - num;
    float local = num / (vn + den);

    // warp reduce
#pragma unroll
    for (int off = 16; off > 0; off >>= 1)
        local += __shfl_down_sync(0xffffffffu, local, off);

    __shared__ float red[8];
    const int lane = threadIdx.x & 31;
    const int wid  = threadIdx.x >> 5;
    if (lane == 0) red[wid] = local;
    __syncthreads();
    if (wid == 0) {
        float v = (lane < 8) ? red[lane] : 0.f;
#pragma unroll
        for (int off = 4; off > 0; off >>= 1)
            v += __shfl_down_sync(0xffffffffu, v, off);
        if (lane == 0) atomicAdd(out, -v / (float)KK);
    }
}

// ---------------------------------------------------------------------------
extern "C" void kernel_launch(void* const* d_in, const int* in_sizes, int n_in,
                              void* d_out, int out_size) {
    const float* zs = (const float*)d_in[0];   // [64, 4096]
    const float* X  = (const float*)d_in[1];   // [4096, 4096]
    const float* vn = (const float*)d_in[2];   // scalar
    float* out = (float*)d_out;

    dim3 grid(NN / BI, SPLIT);                 // 64 x 2 = 128 blocks
    gemm_kernel<<<grid, 256>>>(zs, X);
    zero_out_kernel<<<1, 1>>>(out);
    finish_kernel<<<(KK * NN) / 256, 256>>>(zs, X, vn, out);
}

// round 5
// speedup vs baseline: 3.2924x; 3.2924x over previous
#include <cuda_runtime.h>
#include <cuda_bf16.h>
#include <cstdint>

#define KK 64
#define NN 4096
#define MTILE 128
#define KC 32                          // n-elements per chunk
#define KSPLIT 4
#define NCHUNK ((NN / KSPLIT) / KC)    // 32
#define SROW 40                        // smem row stride in bf16 elems (80 B)

// Partial row_sums: [KSPLIT][KK][NN] fp32 = 4 MB
__device__ float g_partial[KSPLIT * KK * NN];

static __device__ __forceinline__ uint32_t smem_u32(const void* p) {
    uint32_t a;
    asm("{ .reg .u64 t; cvta.to.shared.u64 t, %1; cvt.u32.u64 %0, t; }"
        : "=r"(a) : "l"(p));
    return a;
}
static __device__ __forceinline__ uint32_t pack2(float a, float b) {
    __nv_bfloat162 h = __floats2bfloat162_rn(a, b);
    return *reinterpret_cast<uint32_t*>(&h);
}
static __device__ __forceinline__ void sts128(uint32_t a, uint32_t x, uint32_t y,
                                              uint32_t z, uint32_t w) {
    asm volatile("st.shared.v4.b32 [%0], {%1,%2,%3,%4};"
                 :: "r"(a), "r"(x), "r"(y), "r"(z), "r"(w) : "memory");
}
static __device__ __forceinline__ void ldsm4(uint32_t addr, uint32_t& r0, uint32_t& r1,
                                             uint32_t& r2, uint32_t& r3) {
    asm volatile("ldmatrix.sync.aligned.m8n8.x4.shared.b16 {%0,%1,%2,%3}, [%4];"
                 : "=r"(r0), "=r"(r1), "=r"(r2), "=r"(r3) : "r"(addr));
}
static __device__ __forceinline__ void mma16816(float& c0, float& c1, float& c2, float& c3,
                                                uint32_t a0, uint32_t a1, uint32_t a2,
                                                uint32_t a3, uint32_t b0, uint32_t b1) {
    asm volatile("mma.sync.aligned.m16n8k16.row.col.f32.bf16.bf16.f32 "
                 "{%0,%1,%2,%3}, {%4,%5,%6,%7}, {%8,%9}, {%0,%1,%2,%3};"
                 : "+f"(c0), "+f"(c1), "+f"(c2), "+f"(c3)
                 : "r"(a0), "r"(a1), "r"(a2), "r"(a3), "r"(b0), "r"(b1));
}

// ---------------------------------------------------------------------------
// HMMA GEMM: g_partial[by][k][i] = sum_{n in split by} zs[k][n] * X[i][n]
// grid = (32, KSPLIT), block = 256 (8 warps: 4 i-groups x 2 k-groups)
// ---------------------------------------------------------------------------
__global__ __launch_bounds__(256)
void gemm_hmma(const float* __restrict__ zs, const float* __restrict__ X) {
    // smem: X tiles [2][128][SROW] bf16, zs tiles [2][64][SROW] bf16
    __shared__ __align__(16) __nv_bfloat16 Xs[2][MTILE * SROW];
    __shared__ __align__(16) __nv_bfloat16 Zs[2][KK * SROW];

    const int tid   = threadIdx.x;
    const int lane  = tid & 31;
    const int wid   = tid >> 5;
    const int ibase = blockIdx.x * MTILE;
    const int nbase = blockIdx.y * (NN / KSPLIT);

    const uint32_t XsA[2] = { smem_u32(Xs[0]), smem_u32(Xs[1]) };
    const uint32_t ZsA[2] = { smem_u32(Zs[0]), smem_u32(Zs[1]) };

    // ---- producer assignments (8-float units) ----
    // X chunk: 128 rows x 32 n = 512 units, 2/thread. zs: 64 x 32 = 256 units, 1/thread.
    const int xu0 = tid, xu1 = tid + 256;
    const int xrow0 = xu0 >> 2, xqc0 = xu0 & 3;
    const int xrow1 = xu1 >> 2, xqc1 = xu1 & 3;
    const float* xp0 = X + (size_t)(ibase + xrow0) * NN + nbase + xqc0 * 8;
    const float* xp1 = X + (size_t)(ibase + xrow1) * NN + nbase + xqc1 * 8;
    const uint32_t xs0 = xrow0 * (SROW * 2) + xqc0 * 16;
    const uint32_t xs1 = xrow1 * (SROW * 2) + xqc1 * 16;
    const int zrow = tid >> 2, zqc = tid & 3;
    const float* zp = zs + (size_t)zrow * NN + nbase + zqc * 8;
    const uint32_t zsto = zrow * (SROW * 2) + zqc * 16;

    // ---- consumer (ldmatrix) address components ----
    const int wi = (wid & 3) * 32;           // i group
    const int wj = (wid >> 2) * 32;          // k(j) group
    // A: row = wi + h*16 + (lane&15), 16B col = (lane>>4) + s*2
    const uint32_t a_row = wi + (lane & 15);
    const uint32_t a_col16 = (lane >> 4);
    // B: j = wj + g*16 + ((lane>>4)&1)*8 + (lane&7), 16B col = ((lane>>3)&1) + s*2
    const uint32_t b_row = wj + ((lane >> 4) & 1) * 8 + (lane & 7);
    const uint32_t b_col16 = ((lane >> 3) & 1);

    float acc[2][4][4];
#pragma unroll
    for (int m = 0; m < 2; ++m)
#pragma unroll
        for (int n = 0; n < 4; ++n)
#pragma unroll
            for (int q = 0; q < 4; ++q) acc[m][n][q] = 0.f;

    // prefetch chunk 0
    float4 xr[4], zr[2];
    xr[0] = *(const float4*)(xp0);     xr[1] = *(const float4*)(xp0 + 4);
    xr[2] = *(const float4*)(xp1);     xr[3] = *(const float4*)(xp1 + 4);
    zr[0] = *(const float4*)(zp);      zr[1] = *(const float4*)(zp + 4);

#pragma unroll 1
    for (int c = 0; c < NCHUNK; ++c) {
        const int buf = c & 1;

        // convert + store staged regs into smem
        sts128(XsA[buf] + xs0, pack2(xr[0].x, xr[0].y), pack2(xr[0].z, xr[0].w),
                               pack2(xr[1].x, xr[1].y), pack2(xr[1].z, xr[1].w));
        sts128(XsA[buf] + xs1, pack2(xr[2].x, xr[2].y), pack2(xr[2].z, xr[2].w),
                               pack2(xr[3].x, xr[3].y), pack2(xr[3].z, xr[3].w));
        sts128(ZsA[buf] + zsto, pack2(zr[0].x, zr[0].y), pack2(zr[0].z, zr[0].w),
                                pack2(zr[1].x, zr[1].y), pack2(zr[1].z, zr[1].w));
        __syncthreads();

        // prefetch next chunk (overlaps with MMA below)
        if (c + 1 < NCHUNK) {
            const int off = (c + 1) * KC;
            xr[0] = *(const float4*)(xp0 + off);  xr[1] = *(const float4*)(xp0 + off + 4);
            xr[2] = *(const float4*)(xp1 + off);  xr[3] = *(const float4*)(xp1 + off + 4);
            zr[0] = *(const float4*)(zp + off);   zr[1] = *(const float4*)(zp + off + 4);
        }

        // 2 k16 steps per chunk
#pragma unroll
        for (int s = 0; s < 2; ++s) {
            uint32_t a[2][4], b[2][4];
#pragma unroll
            for (int h = 0; h < 2; ++h)
                ldsm4(XsA[buf] + (a_row + h * 16) * (SROW * 2) + (a_col16 + s * 2) * 16,
                      a[h][0], a[h][1], a[h][2], a[h][3]);
#pragma unroll
            for (int g = 0; g < 2; ++g)
                ldsm4(ZsA[buf] + (b_row + g * 16) * (SROW * 2) + (b_col16 + s * 2) * 16,
                      b[g][0], b[g][1], b[g][2], b[g][3]);
#pragma unroll
            for (int m = 0; m < 2; ++m)
#pragma unroll
                for (int n = 0; n < 4; ++n) {
                    const int g = n >> 1, hi = (n & 1) * 2;
                    mma16816(acc[m][n][0], acc[m][n][1], acc[m][n][2], acc[m][n][3],
                             a[m][0], a[m][1], a[m][2], a[m][3],
                             b[g][hi], b[g][hi + 1]);
                }
        }
        __syncthreads();
    }

    // epilogue: write warp tile to g_partial[by][j][i]
    float* part = g_partial + (size_t)blockIdx.y * (KK * NN);
#pragma unroll
    for (int m = 0; m < 2; ++m) {
        const int i0 = ibase + wi + m * 16 + (lane >> 2);
#pragma unroll
        for (int n = 0; n < 4; ++n) {
            const int j0 = wj + n * 8 + (lane & 3) * 2;
            part[(size_t)j0 * NN + i0]           = acc[m][n][0];
            part[(size_t)(j0 + 1) * NN + i0]     = acc[m][n][1];
            part[(size_t)j0 * NN + i0 + 8]       = acc[m][n][2];
            part[(size_t)(j0 + 1) * NN + i0 + 8] = acc[m][n][3];
        }
    }
}

// ---------------------------------------------------------------------------
__global__ void zero_out_kernel(float* out) { out[0] = 0.f; }

__global__ __launch_bounds__(256)
void finish_kernel(const float* __restrict__ zs, const float* __restrict__ X,
                   const float* __restrict__ vn_p, float* __restrict__ out) {
    const int idx = blockIdx.x * blockDim.x + threadIdx.x;  // covers KK*NN exactly
    const float vn = *vn_p;
    const int i = idx & (NN - 1);

    float rs = g_partial[idx];
#pragma unroll
    for (int s = 1; s < KSPLIT; ++s) rs += g_partial[idx + s * (KK * NN)];

    const float z   = zs[idx];
    const float xd  = X[(size_t)i * NN + i];
    const float num = z * xd;
    const float den = rs - num;
    float local = num / (vn + den);

#pragma unroll
    for (int off = 16; off > 0; off >>= 1)
        local += __shfl_down_sync(0xffffffffu, local, off);

    __shared__ float red[8];
    const int lane = threadIdx.x & 31;
    const int wd   = threadIdx.x >> 5;
    if (lane == 0) red[wd] = local;
    __syncthreads();
    if (wd == 0) {
        float v = (lane < 8) ? red[lane] : 0.f;
#pragma unroll
        for (int off = 4; off > 0; off >>= 1)
            v += __shfl_down_sync(0xffffffffu, v, off);
        if (lane == 0) atomicAdd(out, -v / (float)KK);
    }
}

// ---------------------------------------------------------------------------
extern "C" void kernel_launch(void* const* d_in, const int* in_sizes, int n_in,
                              void* d_out, int out_size) {
    const float* zs = (const float*)d_in[0];   // [64, 4096]
    const float* X  = (const float*)d_in[1];   // [4096, 4096]
    const float* vn = (const float*)d_in[2];   // scalar
    float* out = (float*)d_out;

    dim3 grid(NN / MTILE, KSPLIT);             // 32 x 4 = 128 CTAs
    gemm_hmma<<<grid, 256>>>(zs, X);
    zero_out_kernel<<<1, 1>>>(out);
    finish_kernel<<<(KK * NN) / 256, 256>>>(zs, X, vn, out);
}

// round 6
// speedup vs baseline: 3.7580x; 1.1414x over previous
#include <cuda_runtime.h>
#include <cuda_bf16.h>
#include <cstdint>

#define KK 64
#define NN 4096
#define MTILE 128
#define KC 32                          // n-elements per chunk
#define KSPLIT 8
#define NCHUNK ((NN / KSPLIT) / KC)    // 16
#define SROW 40                        // smem row stride in bf16 elems (80 B)

// Partial row_sums: [KSPLIT][KK][NN] fp32 = 8 MB
__device__ float g_partial[KSPLIT * KK * NN];

static __device__ __forceinline__ uint32_t smem_u32(const void* p) {
    uint32_t a;
    asm("{ .reg .u64 t; cvta.to.shared.u64 t, %1; cvt.u32.u64 %0, t; }"
        : "=r"(a) : "l"(p));
    return a;
}
static __device__ __forceinline__ uint32_t pack2(float a, float b) {
    __nv_bfloat162 h = __floats2bfloat162_rn(a, b);
    return *reinterpret_cast<uint32_t*>(&h);
}
static __device__ __forceinline__ void sts128(uint32_t a, uint32_t x, uint32_t y,
                                              uint32_t z, uint32_t w) {
    asm volatile("st.shared.v4.b32 [%0], {%1,%2,%3,%4};"
                 :: "r"(a), "r"(x), "r"(y), "r"(z), "r"(w) : "memory");
}
static __device__ __forceinline__ void ldsm4(uint32_t addr, uint32_t& r0, uint32_t& r1,
                                             uint32_t& r2, uint32_t& r3) {
    asm volatile("ldmatrix.sync.aligned.m8n8.x4.shared.b16 {%0,%1,%2,%3}, [%4];"
                 : "=r"(r0), "=r"(r1), "=r"(r2), "=r"(r3) : "r"(addr));
}
static __device__ __forceinline__ void mma16816(float& c0, float& c1, float& c2, float& c3,
                                                uint32_t a0, uint32_t a1, uint32_t a2,
                                                uint32_t a3, uint32_t b0, uint32_t b1) {
    asm volatile("mma.sync.aligned.m16n8k16.row.col.f32.bf16.bf16.f32 "
                 "{%0,%1,%2,%3}, {%4,%5,%6,%7}, {%8,%9}, {%0,%1,%2,%3};"
                 : "+f"(c0), "+f"(c1), "+f"(c2), "+f"(c3)
                 : "r"(a0), "r"(a1), "r"(a2), "r"(a3), "r"(b0), "r"(b1));
}

// ---------------------------------------------------------------------------
// HMMA GEMM: g_partial[by][k][i] = sum_{n in split by} zs[k][n] * X[i][n]
// grid = (32, KSPLIT) = 256 CTAs, block = 256 (8 warps: 4 i-groups x 2 k-groups)
// 2 CTAs co-resident per SM so one CTA's compute hides the other's DRAM stall.
// ---------------------------------------------------------------------------
__global__ __launch_bounds__(256, 2)
void gemm_hmma(const float* __restrict__ zs, const float* __restrict__ X) {
    // smem: X tiles [2][128][SROW] bf16, zs tiles [2][64][SROW] bf16  (~30 KB)
    __shared__ __align__(16) __nv_bfloat16 Xs[2][MTILE * SROW];
    __shared__ __align__(16) __nv_bfloat16 Zs[2][KK * SROW];

    const int tid   = threadIdx.x;
    const int lane  = tid & 31;
    const int wid   = tid >> 5;
    const int ibase = blockIdx.x * MTILE;
    const int nbase = blockIdx.y * (NN / KSPLIT);

    const uint32_t XsA[2] = { smem_u32(Xs[0]), smem_u32(Xs[1]) };
    const uint32_t ZsA[2] = { smem_u32(Zs[0]), smem_u32(Zs[1]) };

    // ---- producer assignments (8-float units) ----
    // X chunk: 128 rows x 32 n = 512 units, 2/thread. zs: 64 x 32 = 256 units, 1/thread.
    const int xu0 = tid, xu1 = tid + 256;
    const int xrow0 = xu0 >> 2, xqc0 = xu0 & 3;
    const int xrow1 = xu1 >> 2, xqc1 = xu1 & 3;
    const float* xp0 = X + (size_t)(ibase + xrow0) * NN + nbase + xqc0 * 8;
    const float* xp1 = X + (size_t)(ibase + xrow1) * NN + nbase + xqc1 * 8;
    const uint32_t xs0 = xrow0 * (SROW * 2) + xqc0 * 16;
    const uint32_t xs1 = xrow1 * (SROW * 2) + xqc1 * 16;
    const int zrow = tid >> 2, zqc = tid & 3;
    const float* zp = zs + (size_t)zrow * NN + nbase + zqc * 8;
    const uint32_t zsto = zrow * (SROW * 2) + zqc * 16;

    // ---- consumer (ldmatrix) address components ----
    const int wi = (wid & 3) * 32;           // i group
    const int wj = (wid >> 2) * 32;          // k(j) group
    const uint32_t a_row = wi + (lane & 15);
    const uint32_t a_col16 = (lane >> 4);
    const uint32_t b_row = wj + ((lane >> 4) & 1) * 8 + (lane & 7);
    const uint32_t b_col16 = ((lane >> 3) & 1);

    float acc[2][4][4];
#pragma unroll
    for (int m = 0; m < 2; ++m)
#pragma unroll
        for (int n = 0; n < 4; ++n)
#pragma unroll
            for (int q = 0; q < 4; ++q) acc[m][n][q] = 0.f;

    // prefetch chunk 0
    float4 xr[4], zr[2];
    xr[0] = *(const float4*)(xp0);     xr[1] = *(const float4*)(xp0 + 4);
    xr[2] = *(const float4*)(xp1);     xr[3] = *(const float4*)(xp1 + 4);
    zr[0] = *(const float4*)(zp);      zr[1] = *(const float4*)(zp + 4);

#pragma unroll 1
    for (int c = 0; c < NCHUNK; ++c) {
        const int buf = c & 1;

        // convert + store staged regs into smem
        sts128(XsA[buf] + xs0, pack2(xr[0].x, xr[0].y), pack2(xr[0].z, xr[0].w),
                               pack2(xr[1].x, xr[1].y), pack2(xr[1].z, xr[1].w));
        sts128(XsA[buf] + xs1, pack2(xr[2].x, xr[2].y), pack2(xr[2].z, xr[2].w),
                               pack2(xr[3].x, xr[3].y), pack2(xr[3].z, xr[3].w));
        sts128(ZsA[buf] + zsto, pack2(zr[0].x, zr[0].y), pack2(zr[0].z, zr[0].w),
                                pack2(zr[1].x, zr[1].y), pack2(zr[1].z, zr[1].w));
        __syncthreads();

        // prefetch next chunk (overlaps with MMA below + the co-resident CTA)
        if (c + 1 < NCHUNK) {
            const int off = (c + 1) * KC;
            xr[0] = *(const float4*)(xp0 + off);  xr[1] = *(const float4*)(xp0 + off + 4);
            xr[2] = *(const float4*)(xp1 + off);  xr[3] = *(const float4*)(xp1 + off + 4);
            zr[0] = *(const float4*)(zp + off);   zr[1] = *(const float4*)(zp + off + 4);
        }

        // 2 k16 steps per chunk
#pragma unroll
        for (int s = 0; s < 2; ++s) {
            uint32_t a[2][4], b[2][4];
#pragma unroll
            for (int h = 0; h < 2; ++h)
                ldsm4(XsA[buf] + (a_row + h * 16) * (SROW * 2) + (a_col16 + s * 2) * 16,
                      a[h][0], a[h][1], a[h][2], a[h][3]);
#pragma unroll
            for (int g = 0; g < 2; ++g)
                ldsm4(ZsA[buf] + (b_row + g * 16) * (SROW * 2) + (b_col16 + s * 2) * 16,
                      b[g][0], b[g][1], b[g][2], b[g][3]);
#pragma unroll
            for (int m = 0; m < 2; ++m)
#pragma unroll
                for (int n = 0; n < 4; ++n) {
                    const int g = n >> 1, hi = (n & 1) * 2;
                    mma16816(acc[m][n][0], acc[m][n][1], acc[m][n][2], acc[m][n][3],
                             a[m][0], a[m][1], a[m][2], a[m][3],
                             b[g][hi], b[g][hi + 1]);
                }
        }
        __syncthreads();
    }

    // epilogue: write warp tile to g_partial[by][j][i]
    float* part = g_partial + (size_t)blockIdx.y * (KK * NN);
#pragma unroll
    for (int m = 0; m < 2; ++m) {
        const int i0 = ibase + wi + m * 16 + (lane >> 2);
#pragma unroll
        for (int n = 0; n < 4; ++n) {
            const int j0 = wj + n * 8 + (lane & 3) * 2;
            part[(size_t)j0 * NN + i0]           = acc[m][n][0];
            part[(size_t)(j0 + 1) * NN + i0]     = acc[m][n][1];
            part[(size_t)j0 * NN + i0 + 8]       = acc[m][n][2];
            part[(size_t)(j0 + 1) * NN + i0 + 8] = acc[m][n][3];
        }
    }
}

// ---------------------------------------------------------------------------
__global__ void zero_out_kernel(float* out) { out[0] = 0.f; }

__global__ __launch_bounds__(256)
void finish_kernel(const float* __restrict__ zs, const float* __restrict__ X,
                   const float* __restrict__ vn_p, float* __restrict__ out) {
    const int idx = blockIdx.x * blockDim.x + threadIdx.x;  // covers KK*NN exactly
    const float vn = *vn_p;
    const int i = idx & (NN - 1);

    float rs = g_partial[idx];
#pragma unroll
    for (int s = 1; s < KSPLIT; ++s) rs += g_partial[idx + s * (KK * NN)];

    const float z   = zs[idx];
    const float xd  = X[(size_t)i * NN + i];
    const float num = z * xd;
    const float den = rs - num;
    float local = num / (vn + den);

#pragma unroll
    for (int off = 16; off > 0; off >>= 1)
        local += __shfl_down_sync(0xffffffffu, local, off);

    __shared__ float red[8];
    const int lane = threadIdx.x & 31;
    const int wd   = threadIdx.x >> 5;
    if (lane == 0) red[wd] = local;
    __syncthreads();
    if (wd == 0) {
        float v = (lane < 8) ? red[lane] : 0.f;
#pragma unroll
        for (int off = 4; off > 0; off >>= 1)
            v += __shfl_down_sync(0xffffffffu, v, off);
        if (lane == 0) atomicAdd(out, -v / (float)KK);
    }
}

// ---------------------------------------------------------------------------
extern "C" void kernel_launch(void* const* d_in, const int* in_sizes, int n_in,
                              void* d_out, int out_size) {
    const float* zs = (const float*)d_in[0];   // [64, 4096]
    const float* X  = (const float*)d_in[1];   // [4096, 4096]
    const float* vn = (const float*)d_in[2];   // scalar
    float* out = (float*)d_out;

    dim3 grid(NN / MTILE, KSPLIT);             // 32 x 8 = 256 CTAs
    gemm_hmma<<<grid, 256>>>(zs, X);
    zero_out_kernel<<<1, 1>>>(out);
    finish_kernel<<<(KK * NN) / 256, 256>>>(zs, X, vn, out);
}